// round 4
// baseline (speedup 1.0000x reference)
#include <cuda_runtime.h>
#include <cuda_bf16.h>
#include <math.h>

#define NA    900
#define NTEMP 600
#define ED    256
#define NC    6
#define NL    4
#define NP    13
#define NG    8
#define NLEARN 6
#define NDEC  6
#define ADIM  11
#define NCLS  10
#define WTOT  (NC*NL*NP*NG)   // 2496
#define NSEL  (NA-NTEMP)      // 300
#define NITEM (NL*NP*NC)      // 312

typedef unsigned long long ull;

// -------- output layout (flattened tuple, float32) --------
#define OFF_INST   0
#define OFF_ANCHOR (NA*ED)
#define OFF_CLS    (OFF_ANCHOR + NA*ADIM)
#define OFF_QT     (OFF_CLS + NA*NCLS)
#define OFF_TRACK  (OFF_QT + NA)
#define OFF_TMP    (OFF_TRACK + NA)

// -------- scratch --------
__device__ __align__(16) float g_instA[NA*ED];
__device__ __align__(16) float g_instB[NA*ED];
__device__ __align__(16) float g_anchorA[NA*ADIM];
__device__ __align__(16) float g_anchorB[NA*ADIM];
__device__ __align__(16) float g_embed[NA*ED];
__device__ __align__(16) float g_uv[NA*NP*NC*2];
__device__ __align__(16) float g_W[NA*WTOT];
__device__ __align__(16) float g_cls[NA*NCLS];
__device__ int g_sel[NA];

__constant__ float c_FIX[7][3] = {
    {0.f,0.f,0.f},{0.5f,0.f,0.f},{-0.5f,0.f,0.f},
    {0.f,0.5f,0.f},{0.f,-0.5f,0.f},{0.f,0.f,0.5f},{0.f,0.f,-0.5f}};

// ---- f32x2 helpers ----
__device__ __forceinline__ ull pack2(float x, float y) {
    ull r;
    asm("mov.b64 %0, {%1, %2};" : "=l"(r) : "f"(x), "f"(y));
    return r;
}
__device__ __forceinline__ void unpack2(ull v, float& x, float& y) {
    asm("mov.b64 {%0, %1}, %2;" : "=f"(x), "=f"(y) : "l"(v));
}
__device__ __forceinline__ void ffma2(ull& acc, ull a, ull b) {
    asm("fma.rn.f32x2 %0, %1, %2, %0;" : "+l"(acc) : "l"(a), "l"(b));
}

// ===================== init =====================
__global__ void k_init(const float* __restrict__ inst_in,
                       const float* __restrict__ anchor_in)
{
    int i = blockIdx.x*blockDim.x + threadIdx.x;
    if (i < NA*ED)   g_instA[i]   = inst_in[i];
    if (i < NA*ADIM) g_anchorA[i] = anchor_in[i];
}

// ===================== k1: anchor embed + keypoints + projection ==========
__global__ void k1_embed_kps_proj(const float* __restrict__ anchor_w,
                                  const float* __restrict__ anchor_b,
                                  const float* __restrict__ kps_w,   // [256,18]
                                  const float* __restrict__ kps_b,   // [18]
                                  const float* __restrict__ l2i,     // [6,4,4]
                                  const float* __restrict__ image_wh,// [6,2]
                                  int use_b)
{
    int a = blockIdx.x, t = threadIdx.x;
    const float* inst = use_b ? g_instB : g_instA;
    const float* anch = use_b ? g_anchorB : g_anchorA;

    __shared__ float sfeat[ED];
    __shared__ float sanchor[ADIM];
    __shared__ float spart[18][8];
    __shared__ float slearn[18];
    __shared__ float skp[NP][3];

    sfeat[t] = inst[a*ED + t];
    if (t < ADIM) sanchor[t] = anch[a*ADIM + t];
    __syncthreads();

    {
        float e = anchor_b[t];
        #pragma unroll
        for (int j = 0; j < ADIM; j++) e += sanchor[j] * anchor_w[j*ED + t];
        g_embed[a*ED + t] = e;
    }

    if (t < 144) {
        int m = t >> 3, seg = t & 7;
        float s = 0.f;
        int k0 = seg * 32;
        #pragma unroll 8
        for (int k = k0; k < k0+32; k++) s += sfeat[k] * kps_w[k*18 + m];
        spart[m][seg] = s;
    }
    __syncthreads();
    if (t < 18) {
        float s = kps_b[t];
        #pragma unroll
        for (int seg = 0; seg < 8; seg++) s += spart[t][seg];
        slearn[t] = s;
    }
    __syncthreads();

    if (t < NP*3) {
        int p = t/3, d = t%3;
        float center = sanchor[d];
        float size   = expf(sanchor[3+d]);
        float v = (p < 7) ? c_FIX[p][d] : slearn[(p-7)*3 + d];
        skp[p][d] = center + v * size;
    }
    __syncthreads();

    if (t < NP*NC) {
        int p = t / NC, c = t % NC;
        const float* L = &l2i[c*16];
        float kx = skp[p][0], ky = skp[p][1], kz = skp[p][2];
        float p0 = L[0]*kx + L[1]*ky + L[2]*kz  + L[3];
        float p1 = L[4]*kx + L[5]*ky + L[6]*kz  + L[7];
        float p2 = L[8]*kx + L[9]*ky + L[10]*kz + L[11];
        float z  = fmaxf(p2, 1e-5f);
        float u  = p0 / z / image_wh[c*2 + 0];
        float v  = p1 / z / image_wh[c*2 + 1];
        g_uv[((a*NP + p)*NC + c)*2 + 0] = u;
        g_uv[((a*NP + p)*NC + c)*2 + 1] = v;
    }
}

// ===================== k2: wfc GEMM, f32x2 8x6 micro-kernel ================
// [900x256] @ [256x2496], BM=128 BN=96 BK=16, 256 thr, 8x6 per thread
#define BM 128
#define BMP 132     // padded row stride (floats) to avoid STS bank conflicts
#define BN 96
#define BK 16
__global__ void k2_wfc_gemm(const float* __restrict__ Wm,
                            const float* __restrict__ bias,
                            int use_b)
{
    const float* inst = use_b ? g_instB : g_instA;
    __shared__ __align__(16) float As[BK][BMP];  // k-major, rows contiguous
    __shared__ __align__(16) float Bs[BK][BN];

    int tid  = threadIdx.x;
    int tRow = tid >> 4, tCol = tid & 15;        // 16x16
    int m0 = blockIdx.y * BM, n0 = blockIdx.x * BN;

    ull acc[8][3];
    #pragma unroll
    for (int i = 0; i < 8; i++)
        #pragma unroll
        for (int j = 0; j < 3; j++) acc[i][j] = 0ull;

    for (int k0 = 0; k0 < ED; k0 += BK) {
        // ---- load A tile (transpose to k-major) ----
        #pragma unroll
        for (int it = 0; it < 2; it++) {
            int task = tid + it*256;     // 0..511
            int row = task >> 2, kk = (task & 3) * 4;
            int gm = m0 + row;
            float4 av = make_float4(0.f,0.f,0.f,0.f);
            if (gm < NA) {
                float4 x = *(const float4*)&inst[gm*ED + k0 + kk];
                float4 e = *(const float4*)&g_embed[gm*ED + k0 + kk];
                av = make_float4(x.x+e.x, x.y+e.y, x.z+e.z, x.w+e.w);
            }
            As[kk+0][row] = av.x;
            As[kk+1][row] = av.y;
            As[kk+2][row] = av.z;
            As[kk+3][row] = av.w;
        }
        // ---- load B tile ----
        #pragma unroll
        for (int it = 0; it < 3; it++) {
            int lin = tid + it*256;      // 0..767 (16 rows x 48 float2)
            int r = lin / 48, c2 = lin % 48;
            *(float2*)&Bs[r][c2*2] =
                *(const float2*)&Wm[(size_t)(k0 + r)*WTOT + n0 + c2*2];
        }
        __syncthreads();

        #pragma unroll
        for (int k = 0; k < BK; k++) {
            float4 a0 = *(const float4*)&As[k][tRow*8];
            float4 a1 = *(const float4*)&As[k][tRow*8 + 4];
            ull b0 = *(const ull*)&Bs[k][tCol*6 + 0];
            ull b1 = *(const ull*)&Bs[k][tCol*6 + 2];
            ull b2 = *(const ull*)&Bs[k][tCol*6 + 4];
            float ar[8] = {a0.x,a0.y,a0.z,a0.w,a1.x,a1.y,a1.z,a1.w};
            #pragma unroll
            for (int i = 0; i < 8; i++) {
                ull ad = pack2(ar[i], ar[i]);
                ffma2(acc[i][0], ad, b0);
                ffma2(acc[i][1], ad, b1);
                ffma2(acc[i][2], ad, b2);
            }
        }
        __syncthreads();
    }

    float2 bb[3];
    #pragma unroll
    for (int j = 0; j < 3; j++)
        bb[j] = *(const float2*)&bias[n0 + tCol*6 + 2*j];

    #pragma unroll
    for (int i = 0; i < 8; i++) {
        int r = m0 + tRow*8 + i;
        if (r >= NA) continue;
        #pragma unroll
        for (int j = 0; j < 3; j++) {
            float x, y;
            unpack2(acc[i][j], x, y);
            float2 v = make_float2(x + bb[j].x, y + bb[j].y);
            *(float2*)&g_W[(size_t)r*WTOT + n0 + tCol*6 + 2*j] = v;
        }
    }
}

// ===================== k4: fused softmax + DAF with valid-compaction ======
__global__ void k4_daf(const float* __restrict__ feature,
                       const int* __restrict__ ss,
                       const int* __restrict__ lsi,
                       int T,
                       float* __restrict__ feats_out)
{
    int a = blockIdx.x, t = threadIdx.x, g = t >> 5, lane = t & 31;
    __shared__ float sW[WTOT];
    __shared__ float suv[NP*NC*2];
    __shared__ int   sh[12];
    __shared__ int   sBase[NITEM];
    __shared__ int   sWi[NITEM];
    __shared__ int4  sOff[NITEM];
    __shared__ float4 sCw[NITEM];
    __shared__ short sIdx[NITEM];
    __shared__ int   s_nv;

    for (int idx = t; idx < WTOT; idx += 256)    sW[idx]  = g_W[(size_t)a*WTOT + idx];
    for (int idx = t; idx < NP*NC*2; idx += 256) suv[idx] = g_uv[a*NP*NC*2 + idx];
    if (t < 8) sh[t]   = ss[t];
    if (t < 4) sh[8+t] = lsi[t];
    __syncthreads();

    // ---- softmax over 312 entries of group g (warp per group) ----
    {
        float vals[10];
        float mx = -1e30f;
        int cnt = 0;
        for (int j = lane; j < NITEM; j += 32) {
            float v = sW[j*NG + g];
            vals[cnt++] = v;
            mx = fmaxf(mx, v);
        }
        #pragma unroll
        for (int o = 16; o; o >>= 1) mx = fmaxf(mx, __shfl_xor_sync(0xffffffffu, mx, o));
        float sum = 0.f;
        for (int i = 0; i < cnt; i++) { vals[i] = expf(vals[i] - mx); sum += vals[i]; }
        #pragma unroll
        for (int o = 16; o; o >>= 1) sum += __shfl_xor_sync(0xffffffffu, sum, o);
        float inv = 1.f / sum;
        cnt = 0;
        for (int j = lane; j < NITEM; j += 32)
            sW[j*NG + g] = vals[cnt++] * inv;
    }

    // ---- precompute per-item offsets/weights ----
    for (int i = t; i < NITEM; i += 256) {
        int c  = i % NC;
        int lp = i / NC;
        int p  = lp % NP;
        int l  = lp / NP;
        int H = sh[l*2], Wd = sh[l*2+1], st = sh[8+l];
        float fH = (float)H, fW = (float)Wd;
        float u = suv[(p*NC + c)*2 + 0];
        float v = suv[(p*NC + c)*2 + 1];
        float x = u*fW - 0.5f, y = v*fH - 0.5f;
        float x0f = floorf(x), y0f = floorf(y);
        float dx = x - x0f, dy = y - y0f;
        float x1f = x0f + 1.f, y1f = y0f + 1.f;
        bool vx0 = (x0f >= 0.f) && (x0f < fW);
        bool vx1 = (x1f >= 0.f) && (x1f < fW);
        bool vy0 = (y0f >= 0.f) && (y0f < fH);
        bool vy1 = (y1f >= 0.f) && (y1f < fH);
        int x0 = vx0 ? (int)x0f : 0;
        int x1 = vx1 ? (int)x1f : 0;
        int y0 = vy0 ? (int)y0f : 0;
        int y1 = vy1 ? (int)y1f : 0;

        float4 w;
        w.x = (vx0 && vy0) ? (1.f-dx)*(1.f-dy) : 0.f;
        w.y = (vx1 && vy0) ? dx*(1.f-dy)       : 0.f;
        w.z = (vx0 && vy1) ? (1.f-dx)*dy       : 0.f;
        w.w = (vx1 && vy1) ? dx*dy             : 0.f;
        int4 o;
        o.x = (y0*Wd + x0)*ED;
        o.y = (y0*Wd + x1)*ED;
        o.z = (y1*Wd + x0)*ED;
        o.w = (y1*Wd + x1)*ED;

        bool any = (w.x != 0.f) | (w.y != 0.f) | (w.z != 0.f) | (w.w != 0.f);
        sBase[i] = any ? (c*T + st)*ED : -1;
        sWi[i]   = (c*52 + l*13 + p)*NG;
        sOff[i]  = o;
        sCw[i]   = w;
    }
    __syncthreads();

    // ---- deterministic warp-scan compaction of valid items ----
    if (t < 32) {
        const int CH = (NITEM + 31) / 32;   // 10
        int start = t * CH;
        int end = start + CH; if (end > NITEM) end = NITEM;
        int cnt = 0;
        for (int i = start; i < end; i++) cnt += (sBase[i] >= 0);
        int x = cnt;
        #pragma unroll
        for (int o = 1; o < 32; o <<= 1) {
            int y = __shfl_up_sync(0xffffffffu, x, o);
            if (t >= o) x += y;
        }
        int pos = x - cnt;
        for (int i = start; i < end; i++)
            if (sBase[i] >= 0) sIdx[pos++] = (short)i;
        if (t == 31) s_nv = x;
    }
    __syncthreads();

    // ---- main aggregation over compacted valid items only ----
    int nv = s_nv;
    float acc = 0.f;
    for (int ii = 0; ii < nv; ii++) {
        int i = sIdx[ii];
        float aw = sW[sWi[i] + g];
        const float* f = feature + sBase[i] + t;
        float4 w = sCw[i];
        int4  o = sOff[i];
        if (w.x != 0.f) acc += f[o.x] * (w.x * aw);
        if (w.y != 0.f) acc += f[o.y] * (w.y * aw);
        if (w.z != 0.f) acc += f[o.z] * (w.z * aw);
        if (w.w != 0.f) acc += f[o.w] * (w.w * aw);
    }
    feats_out[a*ED + t] = acc;
}

// ===================== k5: outp -> ffn(relu) -> heads (f32x2 pairs) =======
#define TR 8
#define TP 10
__global__ void k5_tail(const float* __restrict__ feats,
                        const float* __restrict__ outp_w, const float* __restrict__ outp_b,
                        const float* __restrict__ ffn_w,  const float* __restrict__ ffn_b,
                        const float* __restrict__ reg_w,  const float* __restrict__ reg_b,
                        const float* __restrict__ cls_w,  const float* __restrict__ cls_b,
                        const float* __restrict__ qt_w,   const float* __restrict__ qt_b,
                        const float* __restrict__ time_interval,
                        int use_b, int cls_mode, float* cls_dst,
                        int qt_on, float* qt_dst)
{
    float* inst = use_b ? g_instB : g_instA;
    float* anch = use_b ? g_anchorB : g_anchorA;
    int t = threadIdx.x;
    int r0 = blockIdx.x * TR;

    __shared__ __align__(8) float bufA[ED][TP];
    __shared__ __align__(8) float bufB[ED][TP];
    __shared__ float sHW[ED*ADIM + ED*NCLS + ED];

    for (int idx = t; idx < TR*ED; idx += 256) {
        int r = idx >> 8, col = idx & 255;
        int row = r0 + r;
        bufA[col][r] = (row < NA) ? feats[row*ED + col] : 0.f;
        bufB[col][r] = (row < NA) ? inst[row*ED + col]  : 0.f;
    }
    for (int idx = t; idx < ED*ADIM; idx += 256) sHW[idx] = reg_w[idx];
    bool do_cls = (cls_mode != 0);
    if (do_cls)
        for (int idx = t; idx < ED*NCLS; idx += 256) sHW[ED*ADIM + idx] = cls_w[idx];
    if (qt_on)
        for (int idx = t; idx < ED; idx += 256) sHW[ED*ADIM + ED*NCLS + idx] = qt_w[idx];
    __syncthreads();

    ull accA[4] = {0ull,0ull,0ull,0ull};
    for (int k = 0; k < ED; k++) {
        float wv = outp_w[k*ED + t];
        ull wd = pack2(wv, wv);
        #pragma unroll
        for (int p = 0; p < 4; p++) {
            ull b = *(const ull*)&bufA[k][2*p];
            ffma2(accA[p], wd, b);
        }
    }
    __syncthreads();
    {
        float ob = outp_b[t];
        #pragma unroll
        for (int p = 0; p < 4; p++) {
            float x, y;
            unpack2(accA[p], x, y);
            bufA[t][2*p]   = x + ob;
            bufA[t][2*p+1] = y + ob;
        }
    }
    __syncthreads();

    ull accB[4] = {0ull,0ull,0ull,0ull};
    for (int k = 0; k < ED; k++) {
        float wv = ffn_w[k*ED + t];
        ull wd = pack2(wv, wv);
        #pragma unroll
        for (int p = 0; p < 4; p++) {
            ull b = *(const ull*)&bufA[k][2*p];
            ffma2(accB[p], wd, b);
        }
    }
    for (int k = 0; k < ED; k++) {
        float wv = ffn_w[(ED + k)*ED + t];
        ull wd = pack2(wv, wv);
        #pragma unroll
        for (int p = 0; p < 4; p++) {
            ull b = *(const ull*)&bufB[k][2*p];
            ffma2(accB[p], wd, b);
        }
    }
    __syncthreads();
    {
        float fb = ffn_b[t];
        #pragma unroll
        for (int p = 0; p < 4; p++) {
            float x, y;
            unpack2(accB[p], x, y);
            x = fmaxf(x + fb, 0.f);
            y = fmaxf(y + fb, 0.f);
            bufA[t][2*p]   = x;
            bufA[t][2*p+1] = y;
            int rowx = r0 + 2*p, rowy = r0 + 2*p + 1;
            if (rowx < NA) inst[rowx*ED + t] = x;
            if (rowy < NA) inst[rowy*ED + t] = y;
        }
    }
    __syncthreads();

    float ti = time_interval[0];
    for (int o = t; o < TR*ADIM; o += 256) {
        int r = o / ADIM, j = o % ADIM;
        int row = r0 + r;
        if (row < NA) {
            float s = reg_b[j];
            for (int k = 0; k < ED; k++) s += bufA[k][r] * sHW[k*ADIM + j];
            if (j >= 8) s /= ti;
            anch[row*ADIM + j] += s;
        }
    }
    if (do_cls) {
        float* cdst = (cls_mode == 1) ? g_cls : cls_dst;
        for (int o = t; o < TR*NCLS; o += 256) {
            int r = o / NCLS, j = o % NCLS;
            int row = r0 + r;
            if (row < NA) {
                float s = cls_b[j];
                for (int k = 0; k < ED; k++) s += bufA[k][r] * sHW[ED*ADIM + k*NCLS + j];
                cdst[row*NCLS + j] = s;
            }
        }
    }
    if (qt_on) {
        for (int o = t; o < TR; o += 256) {
            int row = r0 + o;
            if (row < NA) {
                float s = qt_b[0];
                for (int k = 0; k < ED; k++) s += bufA[k][o] * sHW[ED*ADIM + ED*NCLS + k];
                qt_dst[row] = s;
            }
        }
    }
}

// ===================== rank + gather ===============
__global__ void k_rank()
{
    __shared__ float ssc[NA];
    int t = threadIdx.x;
    if (t < NA) {
        float m = -1e30f;
        #pragma unroll
        for (int j = 0; j < NCLS; j++) m = fmaxf(m, g_cls[t*NCLS + j]);
        ssc[t] = m;
    }
    __syncthreads();
    if (t < NA) {
        float sc = ssc[t];
        int cnt = 0;
        for (int b = 0; b < NA; b++) {
            float sb = ssc[b];
            cnt += (sb > sc) || (sb == sc && b < t);
        }
        if (cnt < NSEL) g_sel[NTEMP + cnt] = t;
    }
}

__global__ void k_gather(const float* __restrict__ temp_inst,
                         const float* __restrict__ temp_anchor,
                         const unsigned char* __restrict__ mask)
{
    int r = blockIdx.x, t = threadIdx.x;
    bool m = mask[0] != 0;
    if (m) {
        if (r < NTEMP) {
            g_instB[r*ED + t] = temp_inst[r*ED + t];
            if (t < ADIM) g_anchorB[r*ADIM + t] = temp_anchor[r*ADIM + t];
        } else {
            int s = g_sel[r];
            g_instB[r*ED + t] = g_instA[s*ED + t];
            if (t < ADIM) g_anchorB[r*ADIM + t] = g_anchorA[s*ADIM + t];
        }
    } else {
        g_instB[r*ED + t] = g_instA[r*ED + t];
        if (t < ADIM) g_anchorB[r*ADIM + t] = g_anchorA[r*ADIM + t];
    }
}

// ===================== finalize ===========================================
__global__ void k_finalize(float* __restrict__ out,
                           const int* __restrict__ track_id,
                           const unsigned char* __restrict__ mask)
{
    int i = blockIdx.x*blockDim.x + threadIdx.x;
    if (i < NA*ED)   out[OFF_INST + i]   = g_instB[i];
    if (i < NA*ADIM) out[OFF_ANCHOR + i] = g_anchorB[i];
    if (i < NA) {
        bool m = mask[0] != 0;
        out[OFF_TRACK + i] = m ? (float)track_id[i] : -1.0f;
    }
}

// ===================== host ===============================================
extern "C" void kernel_launch(void* const* d_in, const int* in_sizes, int n_in,
                              void* d_out, int out_size)
{
    const float* feature      = (const float*)d_in[0];
    const int*   ss           = (const int*)d_in[1];
    const int*   lsi          = (const int*)d_in[2];
    const float* inst_in      = (const float*)d_in[3];
    const float* anchor_in    = (const float*)d_in[4];
    const float* ti           = (const float*)d_in[5];
    const float* temp_inst    = (const float*)d_in[6];
    const float* temp_anchor  = (const float*)d_in[7];
    const unsigned char* mask = (const unsigned char*)d_in[8];
    const int*   track_id     = (const int*)d_in[9];
    const float* image_wh     = (const float*)d_in[10];
    const float* l2i          = (const float*)d_in[11];
    const float* anchor_w     = (const float*)d_in[12];
    const float* anchor_b     = (const float*)d_in[13];
    const float* kps_w        = (const float*)d_in[14];
    const float* kps_b        = (const float*)d_in[15];
    const float* wfc_w        = (const float*)d_in[16];
    const float* wfc_b        = (const float*)d_in[17];
    const float* outp_w       = (const float*)d_in[18];
    const float* outp_b       = (const float*)d_in[19];
    const float* ffn_w        = (const float*)d_in[20];
    const float* ffn_b        = (const float*)d_in[21];
    const float* reg_w        = (const float*)d_in[22];
    const float* reg_b        = (const float*)d_in[23];
    const float* cls_w        = (const float*)d_in[24];
    const float* cls_b        = (const float*)d_in[25];
    const float* qt_w         = (const float*)d_in[26];
    const float* qt_b         = (const float*)d_in[27];

    int T = in_sizes[0] / (NC*ED);
    float* out = (float*)d_out;

    k_init<<<(NA*ED + 255)/256, 256>>>(inst_in, anchor_in);

    for (int i = 0; i < NDEC; i++) {
        int use_b = (i >= 1) ? 1 : 0;

        k1_embed_kps_proj<<<NA, 256>>>(anchor_w, anchor_b,
                                       kps_w + (size_t)i*ED*NLEARN*3,
                                       kps_b + (size_t)i*NLEARN*3,
                                       l2i, image_wh, use_b);

        dim3 g2(WTOT/BN, (NA + BM - 1)/BM);
        k2_wfc_gemm<<<g2, 256>>>(wfc_w + (size_t)i*ED*WTOT,
                                 wfc_b + (size_t)i*WTOT, use_b);

        float* feats = out + OFF_TMP + (size_t)i*NA*ED;
        k4_daf<<<NA, 256>>>(feature, ss, lsi, T, feats);

        int cls_mode = (i == 0) ? 1 : ((i == NDEC-1) ? 2 : 0);
        int qt_on    = (i == NDEC-1) ? 1 : 0;
        k5_tail<<<(NA + TR - 1)/TR, 256>>>(feats,
                    outp_w + (size_t)i*ED*ED,    outp_b + (size_t)i*ED,
                    ffn_w  + (size_t)i*2*ED*ED,  ffn_b  + (size_t)i*ED,
                    reg_w  + (size_t)i*ED*ADIM,  reg_b  + (size_t)i*ADIM,
                    cls_w  + (size_t)i*ED*NCLS,  cls_b  + (size_t)i*NCLS,
                    qt_w   + (size_t)i*ED,       qt_b   + (size_t)i,
                    ti, use_b, cls_mode, out + OFF_CLS, qt_on, out + OFF_QT);

        if (i == 0) {
            k_rank<<<1, 1024>>>();
            k_gather<<<NA, 256>>>(temp_inst, temp_anchor, mask);
        }
    }

    k_finalize<<<(NA*ED + 255)/256, 256>>>(out, track_id, mask);
}

// round 5
// speedup vs baseline: 1.3344x; 1.3344x over previous
#include <cuda_runtime.h>
#include <cuda_bf16.h>
#include <math.h>

#define NA    900
#define NTEMP 600
#define ED    256
#define NC    6
#define NL    4
#define NP    13
#define NG    8
#define NLEARN 6
#define NDEC  6
#define ADIM  11
#define NCLS  10
#define WTOT  (NC*NL*NP*NG)   // 2496
#define NSEL  (NA-NTEMP)      // 300
#define NITEM (NL*NP*NC)      // 312
#define WSTR  313             // transposed softmax row stride

typedef unsigned long long ull;

// -------- output layout (flattened tuple, float32) --------
#define OFF_INST   0
#define OFF_ANCHOR (NA*ED)
#define OFF_CLS    (OFF_ANCHOR + NA*ADIM)
#define OFF_QT     (OFF_CLS + NA*NCLS)
#define OFF_TRACK  (OFF_QT + NA)
#define OFF_TMP    (OFF_TRACK + NA)

// -------- scratch --------
__device__ __align__(16) float g_instA[NA*ED];
__device__ __align__(16) float g_instB[NA*ED];
__device__ __align__(16) float g_anchorA[NA*ADIM];
__device__ __align__(16) float g_anchorB[NA*ADIM];
__device__ __align__(16) float g_embed[NA*ED];
__device__ __align__(16) float g_uv[NA*NP*NC*2];
__device__ __align__(16) float g_W[NA*WTOT];
__device__ __align__(16) float g_cls[NA*NCLS];
__device__ int g_sel[NA];

__constant__ float c_FIX[7][3] = {
    {0.f,0.f,0.f},{0.5f,0.f,0.f},{-0.5f,0.f,0.f},
    {0.f,0.5f,0.f},{0.f,-0.5f,0.f},{0.f,0.f,0.5f},{0.f,0.f,-0.5f}};

// ---- f32x2 helpers ----
__device__ __forceinline__ ull pack2(float x, float y) {
    ull r;
    asm("mov.b64 %0, {%1, %2};" : "=l"(r) : "f"(x), "f"(y));
    return r;
}
__device__ __forceinline__ void unpack2(ull v, float& x, float& y) {
    asm("mov.b64 {%0, %1}, %2;" : "=f"(x), "=f"(y) : "l"(v));
}
__device__ __forceinline__ void ffma2(ull& acc, ull a, ull b) {
    asm("fma.rn.f32x2 %0, %1, %2, %0;" : "+l"(acc) : "l"(a), "l"(b));
}

// ===================== init =====================
__global__ void k_init(const float* __restrict__ inst_in,
                       const float* __restrict__ anchor_in)
{
    int i = blockIdx.x*blockDim.x + threadIdx.x;
    if (i < NA*ED)   g_instA[i]   = inst_in[i];
    if (i < NA*ADIM) g_anchorA[i] = anchor_in[i];
}

// ===================== k1: anchor embed + keypoints + projection ==========
__global__ void k1_embed_kps_proj(const float* __restrict__ anchor_w,
                                  const float* __restrict__ anchor_b,
                                  const float* __restrict__ kps_w,   // [256,18]
                                  const float* __restrict__ kps_b,   // [18]
                                  const float* __restrict__ l2i,     // [6,4,4]
                                  const float* __restrict__ image_wh,// [6,2]
                                  int use_b)
{
    int a = blockIdx.x, t = threadIdx.x;
    const float* inst = use_b ? g_instB : g_instA;
    const float* anch = use_b ? g_anchorB : g_anchorA;

    __shared__ float sfeat[ED];
    __shared__ float sanchor[ADIM];
    __shared__ float spart[18][8];
    __shared__ float slearn[18];
    __shared__ float skp[NP][3];

    sfeat[t] = inst[a*ED + t];
    if (t < ADIM) sanchor[t] = anch[a*ADIM + t];
    __syncthreads();

    {
        float e = anchor_b[t];
        #pragma unroll
        for (int j = 0; j < ADIM; j++) e += sanchor[j] * anchor_w[j*ED + t];
        g_embed[a*ED + t] = e;
    }

    if (t < 144) {
        int m = t >> 3, seg = t & 7;
        float s = 0.f;
        int k0 = seg * 32;
        #pragma unroll 8
        for (int k = k0; k < k0+32; k++) s += sfeat[k] * kps_w[k*18 + m];
        spart[m][seg] = s;
    }
    __syncthreads();
    if (t < 18) {
        float s = kps_b[t];
        #pragma unroll
        for (int seg = 0; seg < 8; seg++) s += spart[t][seg];
        slearn[t] = s;
    }
    __syncthreads();

    if (t < NP*3) {
        int p = t/3, d = t%3;
        float center = sanchor[d];
        float size   = expf(sanchor[3+d]);
        float v = (p < 7) ? c_FIX[p][d] : slearn[(p-7)*3 + d];
        skp[p][d] = center + v * size;
    }
    __syncthreads();

    if (t < NP*NC) {
        int p = t / NC, c = t % NC;
        const float* L = &l2i[c*16];
        float kx = skp[p][0], ky = skp[p][1], kz = skp[p][2];
        float p0 = L[0]*kx + L[1]*ky + L[2]*kz  + L[3];
        float p1 = L[4]*kx + L[5]*ky + L[6]*kz  + L[7];
        float p2 = L[8]*kx + L[9]*ky + L[10]*kz + L[11];
        float z  = fmaxf(p2, 1e-5f);
        float u  = p0 / z / image_wh[c*2 + 0];
        float v  = p1 / z / image_wh[c*2 + 1];
        g_uv[((a*NP + p)*NC + c)*2 + 0] = u;
        g_uv[((a*NP + p)*NC + c)*2 + 1] = v;
    }
}

// ===================== k2: wfc GEMM (R2 config: BM=64 BN=96 BK=16, 4x6) ====
#define BM 64
#define BN 96
#define BK 16
__global__ void k2_wfc_gemm(const float* __restrict__ Wm,
                            const float* __restrict__ bias,
                            int use_b)
{
    const float* inst = use_b ? g_instB : g_instA;
    __shared__ __align__(16) float As[BM][BK];   // m-major
    __shared__ __align__(16) float Bs[BK][BN];   // n contiguous

    int tid  = threadIdx.x;
    int tRow = tid >> 4, tCol = tid & 15;        // 16x16
    int m0 = blockIdx.y * BM, n0 = blockIdx.x * BN;

    ull acc[4][3];
    #pragma unroll
    for (int i = 0; i < 4; i++)
        #pragma unroll
        for (int j = 0; j < 3; j++) acc[i][j] = 0ull;

    int aRow = tid >> 2;         // 0..63
    int aK4  = (tid & 3) * 4;    // 0,4,8,12

    for (int k0 = 0; k0 < ED; k0 += BK) {
        int gm = m0 + aRow;
        float4 av = make_float4(0.f,0.f,0.f,0.f);
        if (gm < NA) {
            float4 x = *(const float4*)&inst[gm*ED + k0 + aK4];
            float4 e = *(const float4*)&g_embed[gm*ED + k0 + aK4];
            av = make_float4(x.x+e.x, x.y+e.y, x.z+e.z, x.w+e.w);
        }
        *(float4*)&As[aRow][aK4] = av;

        #pragma unroll
        for (int it = 0; it < 3; it++) {
            int lin = tid + it*256;      // 0..767 (16 rows x 48 float2)
            int r = lin / 48, c2 = lin % 48;
            *(float2*)&Bs[r][c2*2] =
                *(const float2*)&Wm[(size_t)(k0 + r)*WTOT + n0 + c2*2];
        }
        __syncthreads();

        #pragma unroll
        for (int k = 0; k < BK; k++) {
            ull b0 = *(const ull*)&Bs[k][tCol*6 + 0];
            ull b1 = *(const ull*)&Bs[k][tCol*6 + 2];
            ull b2 = *(const ull*)&Bs[k][tCol*6 + 4];
            #pragma unroll
            for (int i = 0; i < 4; i++) {
                float a = As[tRow*4 + i][k];
                ull ad = pack2(a, a);
                ffma2(acc[i][0], ad, b0);
                ffma2(acc[i][1], ad, b1);
                ffma2(acc[i][2], ad, b2);
            }
        }
        __syncthreads();
    }

    float2 bb[3];
    #pragma unroll
    for (int j = 0; j < 3; j++)
        bb[j] = *(const float2*)&bias[n0 + tCol*6 + 2*j];

    #pragma unroll
    for (int i = 0; i < 4; i++) {
        int r = m0 + tRow*4 + i;
        if (r >= NA) continue;
        #pragma unroll
        for (int j = 0; j < 3; j++) {
            float x, y;
            unpack2(acc[i][j], x, y);
            float2 v = make_float2(x + bb[j].x, y + bb[j].y);
            *(float2*)&g_W[(size_t)r*WTOT + n0 + tCol*6 + 2*j] = v;
        }
    }
}

// ===================== k4: softmax(transposed) + width-4 aggregation ======
__global__ void k4_daf(const float* __restrict__ feature,
                       const int* __restrict__ ss,
                       const int* __restrict__ lsi,
                       int T,
                       float* __restrict__ feats_out)
{
    int a = blockIdx.x, t = threadIdx.x, g8 = t >> 5, lane = t & 31;
    __shared__ float sWt[NG*WSTR];      // [g][witem], conflict-free softmax rows
    __shared__ float suv[NP*NC*2];
    __shared__ int   sh[12];
    __shared__ int   sValid[NITEM];
    __shared__ int   sWi[NITEM];        // witem = c*52 + l*13 + p
    __shared__ int4  sOff[NITEM];       // absolute float4-offsets (base folded, >>2)
    __shared__ float4 sCw[NITEM];
    __shared__ short sIdx[NITEM];
    __shared__ int   s_nv;

    // load g_W transposed: [item*8+g] -> sWt[g*WSTR + item]
    for (int idx = t; idx < WTOT; idx += 256) {
        float v = g_W[(size_t)a*WTOT + idx];
        sWt[(idx & 7)*WSTR + (idx >> 3)] = v;
    }
    for (int idx = t; idx < NP*NC*2; idx += 256) suv[idx] = g_uv[a*NP*NC*2 + idx];
    if (t < 8) sh[t]   = ss[t];
    if (t < 4) sh[8+t] = lsi[t];
    __syncthreads();

    // ---- softmax per group (warp g8 owns row g8): conflict-free ----
    {
        float* row = &sWt[g8*WSTR];
        float vals[10];
        float mx = -1e30f;
        int cnt = 0;
        for (int j = lane; j < NITEM; j += 32) {
            float v = row[j];
            vals[cnt++] = v;
            mx = fmaxf(mx, v);
        }
        #pragma unroll
        for (int o = 16; o; o >>= 1) mx = fmaxf(mx, __shfl_xor_sync(0xffffffffu, mx, o));
        float sum = 0.f;
        for (int i = 0; i < cnt; i++) { vals[i] = __expf(vals[i] - mx); sum += vals[i]; }
        #pragma unroll
        for (int o = 16; o; o >>= 1) sum += __shfl_xor_sync(0xffffffffu, sum, o);
        float inv = 1.f / sum;
        cnt = 0;
        for (int j = lane; j < NITEM; j += 32) row[j] = vals[cnt++] * inv;
    }

    // ---- precompute per-item corner offsets/weights (base folded in) ----
    for (int i = t; i < NITEM; i += 256) {
        int c  = i % NC;
        int lp = i / NC;
        int p  = lp % NP;
        int l  = lp / NP;
        int H = sh[l*2], Wd = sh[l*2+1], st = sh[8+l];
        float fH = (float)H, fW = (float)Wd;
        float u = suv[(p*NC + c)*2 + 0];
        float v = suv[(p*NC + c)*2 + 1];
        float x = u*fW - 0.5f, y = v*fH - 0.5f;
        float x0f = floorf(x), y0f = floorf(y);
        float dx = x - x0f, dy = y - y0f;
        float x1f = x0f + 1.f, y1f = y0f + 1.f;
        bool vx0 = (x0f >= 0.f) && (x0f < fW);
        bool vx1 = (x1f >= 0.f) && (x1f < fW);
        bool vy0 = (y0f >= 0.f) && (y0f < fH);
        bool vy1 = (y1f >= 0.f) && (y1f < fH);
        int x0 = vx0 ? (int)x0f : 0;
        int x1 = vx1 ? (int)x1f : 0;
        int y0 = vy0 ? (int)y0f : 0;
        int y1 = vy1 ? (int)y1f : 0;

        float4 w;
        w.x = (vx0 && vy0) ? (1.f-dx)*(1.f-dy) : 0.f;
        w.y = (vx1 && vy0) ? dx*(1.f-dy)       : 0.f;
        w.z = (vx0 && vy1) ? (1.f-dx)*dy       : 0.f;
        w.w = (vx1 && vy1) ? dx*dy             : 0.f;

        int base = (c*T + st)*ED;   // fits easily in int
        int4 o;
        o.x = (base + (y0*Wd + x0)*ED) >> 2;   // float4 index
        o.y = (base + (y0*Wd + x1)*ED) >> 2;
        o.z = (base + (y1*Wd + x0)*ED) >> 2;
        o.w = (base + (y1*Wd + x1)*ED) >> 2;

        sValid[i] = ((w.x != 0.f) | (w.y != 0.f) | (w.z != 0.f) | (w.w != 0.f)) ? 1 : 0;
        sWi[i]    = c*52 + l*13 + p;
        sOff[i]   = o;
        sCw[i]    = w;
    }
    __syncthreads();

    // ---- deterministic warp-scan compaction (index order preserved) ----
    if (t < 32) {
        const int CH = (NITEM + 31) / 32;   // 10
        int start = t * CH;
        int end = start + CH; if (end > NITEM) end = NITEM;
        int cnt = 0;
        for (int i = start; i < end; i++) cnt += sValid[i];
        int x = cnt;
        #pragma unroll
        for (int o = 1; o < 32; o <<= 1) {
            int y = __shfl_up_sync(0xffffffffu, x, o);
            if (t >= o) x += y;
        }
        int pos = x - cnt;
        for (int i = start; i < end; i++)
            if (sValid[i]) sIdx[pos++] = (short)i;
        if (t == 31) s_nv = x;
    }
    __syncthreads();

    // ---- aggregation: 64 threads, 4 channels each (float4 + 2xFFMA2) ----
    if (t < 64) {
        int g = t >> 3;                      // group of channels 4t..4t+3
        const float4* fb = (const float4*)feature;
        int nv = s_nv;
        ull acc01 = 0ull, acc23 = 0ull;
        for (int ii = 0; ii < nv; ii++) {
            int i = sIdx[ii];
            float aw = sWt[g*WSTR + sWi[i]];
            float4 w = sCw[i];
            int4  o = sOff[i];
            if (w.x != 0.f) {
                float4 f = fb[o.x + t];
                float wc = w.x * aw; ull wd = pack2(wc, wc);
                ffma2(acc01, wd, pack2(f.x, f.y));
                ffma2(acc23, wd, pack2(f.z, f.w));
            }
            if (w.y != 0.f) {
                float4 f = fb[o.y + t];
                float wc = w.y * aw; ull wd = pack2(wc, wc);
                ffma2(acc01, wd, pack2(f.x, f.y));
                ffma2(acc23, wd, pack2(f.z, f.w));
            }
            if (w.z != 0.f) {
                float4 f = fb[o.z + t];
                float wc = w.z * aw; ull wd = pack2(wc, wc);
                ffma2(acc01, wd, pack2(f.x, f.y));
                ffma2(acc23, wd, pack2(f.z, f.w));
            }
            if (w.w != 0.f) {
                float4 f = fb[o.w + t];
                float wc = w.w * aw; ull wd = pack2(wc, wc);
                ffma2(acc01, wd, pack2(f.x, f.y));
                ffma2(acc23, wd, pack2(f.z, f.w));
            }
        }
        float4 r;
        unpack2(acc01, r.x, r.y);
        unpack2(acc23, r.z, r.w);
        *(float4*)&feats_out[a*ED + t*4] = r;
    }
}

// ===================== k5: outp -> ffn(relu) -> heads (f32x2 pairs) =======
#define TR 8
#define TP 10
__global__ void k5_tail(const float* __restrict__ feats,
                        const float* __restrict__ outp_w, const float* __restrict__ outp_b,
                        const float* __restrict__ ffn_w,  const float* __restrict__ ffn_b,
                        const float* __restrict__ reg_w,  const float* __restrict__ reg_b,
                        const float* __restrict__ cls_w,  const float* __restrict__ cls_b,
                        const float* __restrict__ qt_w,   const float* __restrict__ qt_b,
                        const float* __restrict__ time_interval,
                        int use_b, int cls_mode, float* cls_dst,
                        int qt_on, float* qt_dst)
{
    float* inst = use_b ? g_instB : g_instA;
    float* anch = use_b ? g_anchorB : g_anchorA;
    int t = threadIdx.x;
    int r0 = blockIdx.x * TR;

    __shared__ __align__(8) float bufA[ED][TP];
    __shared__ __align__(8) float bufB[ED][TP];
    __shared__ float sHW[ED*ADIM + ED*NCLS + ED];

    for (int idx = t; idx < TR*ED; idx += 256) {
        int r = idx >> 8, col = idx & 255;
        int row = r0 + r;
        bufA[col][r] = (row < NA) ? feats[row*ED + col] : 0.f;
        bufB[col][r] = (row < NA) ? inst[row*ED + col]  : 0.f;
    }
    for (int idx = t; idx < ED*ADIM; idx += 256) sHW[idx] = reg_w[idx];
    bool do_cls = (cls_mode != 0);
    if (do_cls)
        for (int idx = t; idx < ED*NCLS; idx += 256) sHW[ED*ADIM + idx] = cls_w[idx];
    if (qt_on)
        for (int idx = t; idx < ED; idx += 256) sHW[ED*ADIM + ED*NCLS + idx] = qt_w[idx];
    __syncthreads();

    ull accA[4] = {0ull,0ull,0ull,0ull};
    for (int k = 0; k < ED; k++) {
        float wv = outp_w[k*ED + t];
        ull wd = pack2(wv, wv);
        #pragma unroll
        for (int p = 0; p < 4; p++) {
            ull b = *(const ull*)&bufA[k][2*p];
            ffma2(accA[p], wd, b);
        }
    }
    __syncthreads();
    {
        float ob = outp_b[t];
        #pragma unroll
        for (int p = 0; p < 4; p++) {
            float x, y;
            unpack2(accA[p], x, y);
            bufA[t][2*p]   = x + ob;
            bufA[t][2*p+1] = y + ob;
        }
    }
    __syncthreads();

    ull accB[4] = {0ull,0ull,0ull,0ull};
    for (int k = 0; k < ED; k++) {
        float wv = ffn_w[k*ED + t];
        ull wd = pack2(wv, wv);
        #pragma unroll
        for (int p = 0; p < 4; p++) {
            ull b = *(const ull*)&bufA[k][2*p];
            ffma2(accB[p], wd, b);
        }
    }
    for (int k = 0; k < ED; k++) {
        float wv = ffn_w[(ED + k)*ED + t];
        ull wd = pack2(wv, wv);
        #pragma unroll
        for (int p = 0; p < 4; p++) {
            ull b = *(const ull*)&bufB[k][2*p];
            ffma2(accB[p], wd, b);
        }
    }
    __syncthreads();
    {
        float fb = ffn_b[t];
        #pragma unroll
        for (int p = 0; p < 4; p++) {
            float x, y;
            unpack2(accB[p], x, y);
            x = fmaxf(x + fb, 0.f);
            y = fmaxf(y + fb, 0.f);
            bufA[t][2*p]   = x;
            bufA[t][2*p+1] = y;
            int rowx = r0 + 2*p, rowy = r0 + 2*p + 1;
            if (rowx < NA) inst[rowx*ED + t] = x;
            if (rowy < NA) inst[rowy*ED + t] = y;
        }
    }
    __syncthreads();

    float ti = time_interval[0];
    for (int o = t; o < TR*ADIM; o += 256) {
        int r = o / ADIM, j = o % ADIM;
        int row = r0 + r;
        if (row < NA) {
            float s = reg_b[j];
            for (int k = 0; k < ED; k++) s += bufA[k][r] * sHW[k*ADIM + j];
            if (j >= 8) s /= ti;
            anch[row*ADIM + j] += s;
        }
    }
    if (do_cls) {
        float* cdst = (cls_mode == 1) ? g_cls : cls_dst;
        for (int o = t; o < TR*NCLS; o += 256) {
            int r = o / NCLS, j = o % NCLS;
            int row = r0 + r;
            if (row < NA) {
                float s = cls_b[j];
                for (int k = 0; k < ED; k++) s += bufA[k][r] * sHW[ED*ADIM + k*NCLS + j];
                cdst[row*NCLS + j] = s;
            }
        }
    }
    if (qt_on) {
        for (int o = t; o < TR; o += 256) {
            int row = r0 + o;
            if (row < NA) {
                float s = qt_b[0];
                for (int k = 0; k < ED; k++) s += bufA[k][o] * sHW[ED*ADIM + ED*NCLS + k];
                qt_dst[row] = s;
            }
        }
    }
}

// ===================== rank + gather ===============
__global__ void k_rank()
{
    __shared__ float ssc[NA];
    int t = threadIdx.x;
    if (t < NA) {
        float m = -1e30f;
        #pragma unroll
        for (int j = 0; j < NCLS; j++) m = fmaxf(m, g_cls[t*NCLS + j]);
        ssc[t] = m;
    }
    __syncthreads();
    if (t < NA) {
        float sc = ssc[t];
        int cnt = 0;
        for (int b = 0; b < NA; b++) {
            float sb = ssc[b];
            cnt += (sb > sc) || (sb == sc && b < t);
        }
        if (cnt < NSEL) g_sel[NTEMP + cnt] = t;
    }
}

__global__ void k_gather(const float* __restrict__ temp_inst,
                         const float* __restrict__ temp_anchor,
                         const unsigned char* __restrict__ mask)
{
    int r = blockIdx.x, t = threadIdx.x;
    bool m = mask[0] != 0;
    if (m) {
        if (r < NTEMP) {
            g_instB[r*ED + t] = temp_inst[r*ED + t];
            if (t < ADIM) g_anchorB[r*ADIM + t] = temp_anchor[r*ADIM + t];
        } else {
            int s = g_sel[r];
            g_instB[r*ED + t] = g_instA[s*ED + t];
            if (t < ADIM) g_anchorB[r*ADIM + t] = g_anchorA[s*ADIM + t];
        }
    } else {
        g_instB[r*ED + t] = g_instA[r*ED + t];
        if (t < ADIM) g_anchorB[r*ADIM + t] = g_anchorA[r*ADIM + t];
    }
}

// ===================== finalize ===========================================
__global__ void k_finalize(float* __restrict__ out,
                           const int* __restrict__ track_id,
                           const unsigned char* __restrict__ mask)
{
    int i = blockIdx.x*blockDim.x + threadIdx.x;
    if (i < NA*ED)   out[OFF_INST + i]   = g_instB[i];
    if (i < NA*ADIM) out[OFF_ANCHOR + i] = g_anchorB[i];
    if (i < NA) {
        bool m = mask[0] != 0;
        out[OFF_TRACK + i] = m ? (float)track_id[i] : -1.0f;
    }
}

// ===================== host ===============================================
extern "C" void kernel_launch(void* const* d_in, const int* in_sizes, int n_in,
                              void* d_out, int out_size)
{
    const float* feature      = (const float*)d_in[0];
    const int*   ss           = (const int*)d_in[1];
    const int*   lsi          = (const int*)d_in[2];
    const float* inst_in      = (const float*)d_in[3];
    const float* anchor_in    = (const float*)d_in[4];
    const float* ti           = (const float*)d_in[5];
    const float* temp_inst    = (const float*)d_in[6];
    const float* temp_anchor  = (const float*)d_in[7];
    const unsigned char* mask = (const unsigned char*)d_in[8];
    const int*   track_id     = (const int*)d_in[9];
    const float* image_wh     = (const float*)d_in[10];
    const float* l2i          = (const float*)d_in[11];
    const float* anchor_w     = (const float*)d_in[12];
    const float* anchor_b     = (const float*)d_in[13];
    const float* kps_w        = (const float*)d_in[14];
    const float* kps_b        = (const float*)d_in[15];
    const float* wfc_w        = (const float*)d_in[16];
    const float* wfc_b        = (const float*)d_in[17];
    const float* outp_w       = (const float*)d_in[18];
    const float* outp_b       = (const float*)d_in[19];
    const float* ffn_w        = (const float*)d_in[20];
    const float* ffn_b        = (const float*)d_in[21];
    const float* reg_w        = (const float*)d_in[22];
    const float* reg_b        = (const float*)d_in[23];
    const float* cls_w        = (const float*)d_in[24];
    const float* cls_b        = (const float*)d_in[25];
    const float* qt_w         = (const float*)d_in[26];
    const float* qt_b         = (const float*)d_in[27];

    int T = in_sizes[0] / (NC*ED);
    float* out = (float*)d_out;

    k_init<<<(NA*ED + 255)/256, 256>>>(inst_in, anchor_in);

    for (int i = 0; i < NDEC; i++) {
        int use_b = (i >= 1) ? 1 : 0;

        k1_embed_kps_proj<<<NA, 256>>>(anchor_w, anchor_b,
                                       kps_w + (size_t)i*ED*NLEARN*3,
                                       kps_b + (size_t)i*NLEARN*3,
                                       l2i, image_wh, use_b);

        dim3 g2(WTOT/BN, (NA + BM - 1)/BM);
        k2_wfc_gemm<<<g2, 256>>>(wfc_w + (size_t)i*ED*WTOT,
                                 wfc_b + (size_t)i*WTOT, use_b);

        float* feats = out + OFF_TMP + (size_t)i*NA*ED;
        k4_daf<<<NA, 256>>>(feature, ss, lsi, T, feats);

        int cls_mode = (i == 0) ? 1 : ((i == NDEC-1) ? 2 : 0);
        int qt_on    = (i == NDEC-1) ? 1 : 0;
        k5_tail<<<(NA + TR - 1)/TR, 256>>>(feats,
                    outp_w + (size_t)i*ED*ED,    outp_b + (size_t)i*ED,
                    ffn_w  + (size_t)i*2*ED*ED,  ffn_b  + (size_t)i*ED,
                    reg_w  + (size_t)i*ED*ADIM,  reg_b  + (size_t)i*ADIM,
                    cls_w  + (size_t)i*ED*NCLS,  cls_b  + (size_t)i*NCLS,
                    qt_w   + (size_t)i*ED,       qt_b   + (size_t)i,
                    ti, use_b, cls_mode, out + OFF_CLS, qt_on, out + OFF_QT);

        if (i == 0) {
            k_rank<<<1, 1024>>>();
            k_gather<<<NA, 256>>>(temp_inst, temp_anchor, mask);
        }
    }

    k_finalize<<<(NA*ED + 255)/256, 256>>>(out, track_id, mask);
}

// round 6
// speedup vs baseline: 1.5080x; 1.1300x over previous
#include <cuda_runtime.h>
#include <cuda_bf16.h>
#include <math.h>

#define NA    900
#define NTEMP 600
#define ED    256
#define NC    6
#define NL    4
#define NP    13
#define NG    8
#define NLEARN 6
#define NDEC  6
#define ADIM  11
#define NCLS  10
#define WTOT  (NC*NL*NP*NG)   // 2496
#define NSEL  (NA-NTEMP)      // 300
#define NITEM (NL*NP*NC)      // 312
#define WSTR  313             // transposed softmax row stride

typedef unsigned long long ull;

// -------- output layout (flattened tuple, float32) --------
#define OFF_INST   0
#define OFF_ANCHOR (NA*ED)
#define OFF_CLS    (OFF_ANCHOR + NA*ADIM)
#define OFF_QT     (OFF_CLS + NA*NCLS)
#define OFF_TRACK  (OFF_QT + NA)
#define OFF_TMP    (OFF_TRACK + NA)

// -------- scratch --------
__device__ __align__(16) float g_instA[NA*ED];
__device__ __align__(16) float g_instB[NA*ED];
__device__ __align__(16) float g_anchorA[NA*ADIM];
__device__ __align__(16) float g_anchorB[NA*ADIM];
__device__ __align__(16) float g_embed[NA*ED];
__device__ __align__(16) float g_uv[NA*NP*NC*2];
__device__ __align__(16) float g_W[NA*WTOT];
__device__ __align__(16) float g_cls[NA*NCLS];
__device__ int g_sel[NA];

__constant__ float c_FIX[7][3] = {
    {0.f,0.f,0.f},{0.5f,0.f,0.f},{-0.5f,0.f,0.f},
    {0.f,0.5f,0.f},{0.f,-0.5f,0.f},{0.f,0.f,0.5f},{0.f,0.f,-0.5f}};

// ---- f32x2 helpers ----
__device__ __forceinline__ ull pack2(float x, float y) {
    ull r;
    asm("mov.b64 %0, {%1, %2};" : "=l"(r) : "f"(x), "f"(y));
    return r;
}
__device__ __forceinline__ void unpack2(ull v, float& x, float& y) {
    asm("mov.b64 {%0, %1}, %2;" : "=f"(x), "=f"(y) : "l"(v));
}
__device__ __forceinline__ void ffma2(ull& acc, ull a, ull b) {
    asm("fma.rn.f32x2 %0, %1, %2, %0;" : "+l"(acc) : "l"(a), "l"(b));
}

// ===================== init =====================
__global__ void k_init(const float* __restrict__ inst_in,
                       const float* __restrict__ anchor_in)
{
    int i = blockIdx.x*blockDim.x + threadIdx.x;
    if (i < NA*ED)   g_instA[i]   = inst_in[i];
    if (i < NA*ADIM) g_anchorA[i] = anchor_in[i];
}

// ===================== k1: anchor embed + keypoints + projection ==========
__global__ void k1_embed_kps_proj(const float* __restrict__ anchor_w,
                                  const float* __restrict__ anchor_b,
                                  const float* __restrict__ kps_w,   // [256,18]
                                  const float* __restrict__ kps_b,   // [18]
                                  const float* __restrict__ l2i,     // [6,4,4]
                                  const float* __restrict__ image_wh,// [6,2]
                                  int use_b)
{
    int a = blockIdx.x, t = threadIdx.x;
    const float* inst = use_b ? g_instB : g_instA;
    const float* anch = use_b ? g_anchorB : g_anchorA;

    __shared__ float sfeat[ED];
    __shared__ float sanchor[ADIM];
    __shared__ float spart[18][8];
    __shared__ float slearn[18];
    __shared__ float skp[NP][3];

    sfeat[t] = inst[a*ED + t];
    if (t < ADIM) sanchor[t] = anch[a*ADIM + t];
    __syncthreads();

    {
        float e = anchor_b[t];
        #pragma unroll
        for (int j = 0; j < ADIM; j++) e += sanchor[j] * anchor_w[j*ED + t];
        g_embed[a*ED + t] = e;
    }

    if (t < 144) {
        int m = t >> 3, seg = t & 7;
        float s = 0.f;
        int k0 = seg * 32;
        #pragma unroll 8
        for (int k = k0; k < k0+32; k++) s += sfeat[k] * kps_w[k*18 + m];
        spart[m][seg] = s;
    }
    __syncthreads();
    if (t < 18) {
        float s = kps_b[t];
        #pragma unroll
        for (int seg = 0; seg < 8; seg++) s += spart[t][seg];
        slearn[t] = s;
    }
    __syncthreads();

    if (t < NP*3) {
        int p = t/3, d = t%3;
        float center = sanchor[d];
        float size   = expf(sanchor[3+d]);
        float v = (p < 7) ? c_FIX[p][d] : slearn[(p-7)*3 + d];
        skp[p][d] = center + v * size;
    }
    __syncthreads();

    if (t < NP*NC) {
        int p = t / NC, c = t % NC;
        const float* L = &l2i[c*16];
        float kx = skp[p][0], ky = skp[p][1], kz = skp[p][2];
        float p0 = L[0]*kx + L[1]*ky + L[2]*kz  + L[3];
        float p1 = L[4]*kx + L[5]*ky + L[6]*kz  + L[7];
        float p2 = L[8]*kx + L[9]*ky + L[10]*kz + L[11];
        float z  = fmaxf(p2, 1e-5f);
        float u  = p0 / z / image_wh[c*2 + 0];
        float v  = p1 / z / image_wh[c*2 + 1];
        g_uv[((a*NP + p)*NC + c)*2 + 0] = u;
        g_uv[((a*NP + p)*NC + c)*2 + 1] = v;
    }
}

// ===================== k2: wfc GEMM (BM=64 BN=96 BK=16, 4x6, reg pipelined)
#define BM 64
#define BN 96
#define BK 16
__global__ void k2_wfc_gemm(const float* __restrict__ Wm,
                            const float* __restrict__ bias,
                            int use_b)
{
    const float* inst = use_b ? g_instB : g_instA;
    __shared__ __align__(16) float As[BM][BK];   // m-major
    __shared__ __align__(16) float Bs[BK][BN];   // n contiguous

    int tid  = threadIdx.x;
    int tRow = tid >> 4, tCol = tid & 15;        // 16x16
    int m0 = blockIdx.y * BM, n0 = blockIdx.x * BN;

    ull acc[4][3];
    #pragma unroll
    for (int i = 0; i < 4; i++)
        #pragma unroll
        for (int j = 0; j < 3; j++) acc[i][j] = 0ull;

    int aRow = tid >> 2;         // 0..63
    int aK4  = (tid & 3) * 4;    // 0,4,8,12
    int gm   = m0 + aRow;
    bool mok = (gm < NA);

    // B-load mapping: 3 tasks, 16 rows x 48 float2
    int bR[3], bC[3];
    #pragma unroll
    for (int it = 0; it < 3; it++) {
        int lin = tid + it*256;
        bR[it] = lin / 48;
        bC[it] = (lin % 48) * 2;
    }

    // ---- prologue: load tile k0=0 into registers ----
    float4 avr = make_float4(0.f,0.f,0.f,0.f);
    if (mok) {
        float4 x = *(const float4*)&inst[gm*ED + aK4];
        float4 e = *(const float4*)&g_embed[gm*ED + aK4];
        avr = make_float4(x.x+e.x, x.y+e.y, x.z+e.z, x.w+e.w);
    }
    float2 bvr[3];
    #pragma unroll
    for (int it = 0; it < 3; it++)
        bvr[it] = *(const float2*)&Wm[(size_t)bR[it]*WTOT + n0 + bC[it]];

    for (int k0 = 0; k0 < ED; k0 += BK) {
        // store current tile regs -> smem
        *(float4*)&As[aRow][aK4] = avr;
        #pragma unroll
        for (int it = 0; it < 3; it++)
            *(float2*)&Bs[bR[it]][bC[it]] = bvr[it];
        __syncthreads();

        // prefetch next tile into regs (overlaps compute below)
        int k0n = k0 + BK;
        if (k0n < ED) {
            if (mok) {
                float4 x = *(const float4*)&inst[gm*ED + k0n + aK4];
                float4 e = *(const float4*)&g_embed[gm*ED + k0n + aK4];
                avr = make_float4(x.x+e.x, x.y+e.y, x.z+e.z, x.w+e.w);
            }
            #pragma unroll
            for (int it = 0; it < 3; it++)
                bvr[it] = *(const float2*)&Wm[(size_t)(k0n + bR[it])*WTOT + n0 + bC[it]];
        }

        #pragma unroll
        for (int k = 0; k < BK; k++) {
            ull b0 = *(const ull*)&Bs[k][tCol*6 + 0];
            ull b1 = *(const ull*)&Bs[k][tCol*6 + 2];
            ull b2 = *(const ull*)&Bs[k][tCol*6 + 4];
            #pragma unroll
            for (int i = 0; i < 4; i++) {
                float a = As[tRow*4 + i][k];
                ull ad = pack2(a, a);
                ffma2(acc[i][0], ad, b0);
                ffma2(acc[i][1], ad, b1);
                ffma2(acc[i][2], ad, b2);
            }
        }
        __syncthreads();
    }

    float2 bb[3];
    #pragma unroll
    for (int j = 0; j < 3; j++)
        bb[j] = *(const float2*)&bias[n0 + tCol*6 + 2*j];

    #pragma unroll
    for (int i = 0; i < 4; i++) {
        int r = m0 + tRow*4 + i;
        if (r >= NA) continue;
        #pragma unroll
        for (int j = 0; j < 3; j++) {
            float x, y;
            unpack2(acc[i][j], x, y);
            float2 v = make_float2(x + bb[j].x, y + bb[j].y);
            *(float2*)&g_W[(size_t)r*WTOT + n0 + tCol*6 + 2*j] = v;
        }
    }
}

// ===================== k4: softmax + 4-way chunked aggregation ============
__global__ void k4_daf(const float* __restrict__ feature,
                       const int* __restrict__ ss,
                       const int* __restrict__ lsi,
                       int T,
                       float* __restrict__ feats_out)
{
    int a = blockIdx.x, t = threadIdx.x, g8 = t >> 5, lane = t & 31;
    __shared__ float sWt[NG*WSTR];      // [g][witem], conflict-free softmax rows
    __shared__ float suv[NP*NC*2];
    __shared__ int   sh[12];
    __shared__ int   sValid[NITEM];
    __shared__ int   sWi[NITEM];        // witem = c*52 + l*13 + p
    __shared__ int4  sOff[NITEM];       // absolute float4-offsets (base folded, >>2)
    __shared__ float4 sCw[NITEM];
    __shared__ short sIdx[NITEM];
    __shared__ int   s_nv;
    __shared__ __align__(16) float4 sPart[4][64];

    // load g_W transposed: [item*8+g] -> sWt[g*WSTR + item]
    for (int idx = t; idx < WTOT; idx += 256) {
        float v = g_W[(size_t)a*WTOT + idx];
        sWt[(idx & 7)*WSTR + (idx >> 3)] = v;
    }
    for (int idx = t; idx < NP*NC*2; idx += 256) suv[idx] = g_uv[a*NP*NC*2 + idx];
    if (t < 8) sh[t]   = ss[t];
    if (t < 4) sh[8+t] = lsi[t];
    __syncthreads();

    // ---- softmax per group (warp g8 owns row g8): conflict-free ----
    {
        float* row = &sWt[g8*WSTR];
        float vals[10];
        float mx = -1e30f;
        int cnt = 0;
        for (int j = lane; j < NITEM; j += 32) {
            float v = row[j];
            vals[cnt++] = v;
            mx = fmaxf(mx, v);
        }
        #pragma unroll
        for (int o = 16; o; o >>= 1) mx = fmaxf(mx, __shfl_xor_sync(0xffffffffu, mx, o));
        float sum = 0.f;
        for (int i = 0; i < cnt; i++) { vals[i] = __expf(vals[i] - mx); sum += vals[i]; }
        #pragma unroll
        for (int o = 16; o; o >>= 1) sum += __shfl_xor_sync(0xffffffffu, sum, o);
        float inv = 1.f / sum;
        cnt = 0;
        for (int j = lane; j < NITEM; j += 32) row[j] = vals[cnt++] * inv;
    }

    // ---- precompute per-item corner offsets/weights (base folded in) ----
    for (int i = t; i < NITEM; i += 256) {
        int c  = i % NC;
        int lp = i / NC;
        int p  = lp % NP;
        int l  = lp / NP;
        int H = sh[l*2], Wd = sh[l*2+1], st = sh[8+l];
        float fH = (float)H, fW = (float)Wd;
        float u = suv[(p*NC + c)*2 + 0];
        float v = suv[(p*NC + c)*2 + 1];
        float x = u*fW - 0.5f, y = v*fH - 0.5f;
        float x0f = floorf(x), y0f = floorf(y);
        float dx = x - x0f, dy = y - y0f;
        float x1f = x0f + 1.f, y1f = y0f + 1.f;
        bool vx0 = (x0f >= 0.f) && (x0f < fW);
        bool vx1 = (x1f >= 0.f) && (x1f < fW);
        bool vy0 = (y0f >= 0.f) && (y0f < fH);
        bool vy1 = (y1f >= 0.f) && (y1f < fH);
        int x0 = vx0 ? (int)x0f : 0;
        int x1 = vx1 ? (int)x1f : 0;
        int y0 = vy0 ? (int)y0f : 0;
        int y1 = vy1 ? (int)y1f : 0;

        float4 w;
        w.x = (vx0 && vy0) ? (1.f-dx)*(1.f-dy) : 0.f;
        w.y = (vx1 && vy0) ? dx*(1.f-dy)       : 0.f;
        w.z = (vx0 && vy1) ? (1.f-dx)*dy       : 0.f;
        w.w = (vx1 && vy1) ? dx*dy             : 0.f;

        int base = (c*T + st)*ED;
        int4 o;
        o.x = (base + (y0*Wd + x0)*ED) >> 2;
        o.y = (base + (y0*Wd + x1)*ED) >> 2;
        o.z = (base + (y1*Wd + x0)*ED) >> 2;
        o.w = (base + (y1*Wd + x1)*ED) >> 2;

        sValid[i] = ((w.x != 0.f) | (w.y != 0.f) | (w.z != 0.f) | (w.w != 0.f)) ? 1 : 0;
        sWi[i]    = c*52 + l*13 + p;
        sOff[i]   = o;
        sCw[i]    = w;
    }
    __syncthreads();

    // ---- deterministic warp-scan compaction (index order preserved) ----
    if (t < 32) {
        const int CH = (NITEM + 31) / 32;   // 10
        int start = t * CH;
        int end = start + CH; if (end > NITEM) end = NITEM;
        int cnt = 0;
        for (int i = start; i < end; i++) cnt += sValid[i];
        int x = cnt;
        #pragma unroll
        for (int o = 1; o < 32; o <<= 1) {
            int y = __shfl_up_sync(0xffffffffu, x, o);
            if (t >= o) x += y;
        }
        int pos = x - cnt;
        for (int i = start; i < end; i++)
            if (sValid[i]) sIdx[pos++] = (short)i;
        if (t == 31) s_nv = x;
    }
    __syncthreads();

    // ---- aggregation: 4 chunks x 64 threads, 4 channels each ----
    {
        int chunk = t >> 6;                  // 0..3: item stripe
        int ch = t & 63;                     // channel quad 4ch..4ch+3
        int g = ch >> 3;
        const float4* fb = (const float4*)feature;
        int nv = s_nv;
        ull acc01 = 0ull, acc23 = 0ull;
        for (int ii = chunk; ii < nv; ii += 4) {
            int i = sIdx[ii];
            float aw = sWt[g*WSTR + sWi[i]];
            float4 w = sCw[i];
            int4  o = sOff[i];
            if (w.x != 0.f) {
                float4 f = fb[o.x + ch];
                float wc = w.x * aw; ull wd = pack2(wc, wc);
                ffma2(acc01, wd, pack2(f.x, f.y));
                ffma2(acc23, wd, pack2(f.z, f.w));
            }
            if (w.y != 0.f) {
                float4 f = fb[o.y + ch];
                float wc = w.y * aw; ull wd = pack2(wc, wc);
                ffma2(acc01, wd, pack2(f.x, f.y));
                ffma2(acc23, wd, pack2(f.z, f.w));
            }
            if (w.z != 0.f) {
                float4 f = fb[o.z + ch];
                float wc = w.z * aw; ull wd = pack2(wc, wc);
                ffma2(acc01, wd, pack2(f.x, f.y));
                ffma2(acc23, wd, pack2(f.z, f.w));
            }
            if (w.w != 0.f) {
                float4 f = fb[o.w + ch];
                float wc = w.w * aw; ull wd = pack2(wc, wc);
                ffma2(acc01, wd, pack2(f.x, f.y));
                ffma2(acc23, wd, pack2(f.z, f.w));
            }
        }
        float4 r;
        unpack2(acc01, r.x, r.y);
        unpack2(acc23, r.z, r.w);
        sPart[chunk][ch] = r;
    }
    __syncthreads();
    if (t < 64) {
        float4 p0 = sPart[0][t], p1 = sPart[1][t], p2 = sPart[2][t], p3 = sPart[3][t];
        float4 r;
        r.x = ((p0.x + p1.x) + p2.x) + p3.x;
        r.y = ((p0.y + p1.y) + p2.y) + p3.y;
        r.z = ((p0.z + p1.z) + p2.z) + p3.z;
        r.w = ((p0.w + p1.w) + p2.w) + p3.w;
        *(float4*)&feats_out[a*ED + t*4] = r;
    }
}

// ===================== k5: outp -> ffn(relu) -> heads (f32x2 pairs) =======
#define TR 8
#define TP 10
__global__ void k5_tail(const float* __restrict__ feats,
                        const float* __restrict__ outp_w, const float* __restrict__ outp_b,
                        const float* __restrict__ ffn_w,  const float* __restrict__ ffn_b,
                        const float* __restrict__ reg_w,  const float* __restrict__ reg_b,
                        const float* __restrict__ cls_w,  const float* __restrict__ cls_b,
                        const float* __restrict__ qt_w,   const float* __restrict__ qt_b,
                        const float* __restrict__ time_interval,
                        int use_b, int cls_mode, float* cls_dst,
                        int qt_on, float* qt_dst)
{
    float* inst = use_b ? g_instB : g_instA;
    float* anch = use_b ? g_anchorB : g_anchorA;
    int t = threadIdx.x;
    int r0 = blockIdx.x * TR;

    __shared__ __align__(8) float bufA[ED][TP];
    __shared__ __align__(8) float bufB[ED][TP];
    __shared__ float sHW[ED*ADIM + ED*NCLS + ED];

    for (int idx = t; idx < TR*ED; idx += 256) {
        int r = idx >> 8, col = idx & 255;
        int row = r0 + r;
        bufA[col][r] = (row < NA) ? feats[row*ED + col] : 0.f;
        bufB[col][r] = (row < NA) ? inst[row*ED + col]  : 0.f;
    }
    for (int idx = t; idx < ED*ADIM; idx += 256) sHW[idx] = reg_w[idx];
    bool do_cls = (cls_mode != 0);
    if (do_cls)
        for (int idx = t; idx < ED*NCLS; idx += 256) sHW[ED*ADIM + idx] = cls_w[idx];
    if (qt_on)
        for (int idx = t; idx < ED; idx += 256) sHW[ED*ADIM + ED*NCLS + idx] = qt_w[idx];
    __syncthreads();

    ull accA[4] = {0ull,0ull,0ull,0ull};
    for (int k = 0; k < ED; k++) {
        float wv = outp_w[k*ED + t];
        ull wd = pack2(wv, wv);
        #pragma unroll
        for (int p = 0; p < 4; p++) {
            ull b = *(const ull*)&bufA[k][2*p];
            ffma2(accA[p], wd, b);
        }
    }
    __syncthreads();
    {
        float ob = outp_b[t];
        #pragma unroll
        for (int p = 0; p < 4; p++) {
            float x, y;
            unpack2(accA[p], x, y);
            bufA[t][2*p]   = x + ob;
            bufA[t][2*p+1] = y + ob;
        }
    }
    __syncthreads();

    ull accB[4] = {0ull,0ull,0ull,0ull};
    for (int k = 0; k < ED; k++) {
        float wv = ffn_w[k*ED + t];
        ull wd = pack2(wv, wv);
        #pragma unroll
        for (int p = 0; p < 4; p++) {
            ull b = *(const ull*)&bufA[k][2*p];
            ffma2(accB[p], wd, b);
        }
    }
    for (int k = 0; k < ED; k++) {
        float wv = ffn_w[(ED + k)*ED + t];
        ull wd = pack2(wv, wv);
        #pragma unroll
        for (int p = 0; p < 4; p++) {
            ull b = *(const ull*)&bufB[k][2*p];
            ffma2(accB[p], wd, b);
        }
    }
    __syncthreads();
    {
        float fb = ffn_b[t];
        #pragma unroll
        for (int p = 0; p < 4; p++) {
            float x, y;
            unpack2(accB[p], x, y);
            x = fmaxf(x + fb, 0.f);
            y = fmaxf(y + fb, 0.f);
            bufA[t][2*p]   = x;
            bufA[t][2*p+1] = y;
            int rowx = r0 + 2*p, rowy = r0 + 2*p + 1;
            if (rowx < NA) inst[rowx*ED + t] = x;
            if (rowy < NA) inst[rowy*ED + t] = y;
        }
    }
    __syncthreads();

    float ti = time_interval[0];
    for (int o = t; o < TR*ADIM; o += 256) {
        int r = o / ADIM, j = o % ADIM;
        int row = r0 + r;
        if (row < NA) {
            float s = reg_b[j];
            for (int k = 0; k < ED; k++) s += bufA[k][r] * sHW[k*ADIM + j];
            if (j >= 8) s /= ti;
            anch[row*ADIM + j] += s;
        }
    }
    if (do_cls) {
        float* cdst = (cls_mode == 1) ? g_cls : cls_dst;
        for (int o = t; o < TR*NCLS; o += 256) {
            int r = o / NCLS, j = o % NCLS;
            int row = r0 + r;
            if (row < NA) {
                float s = cls_b[j];
                for (int k = 0; k < ED; k++) s += bufA[k][r] * sHW[ED*ADIM + k*NCLS + j];
                cdst[row*NCLS + j] = s;
            }
        }
    }
    if (qt_on) {
        for (int o = t; o < TR; o += 256) {
            int row = r0 + o;
            if (row < NA) {
                float s = qt_b[0];
                for (int k = 0; k < ED; k++) s += bufA[k][o] * sHW[ED*ADIM + ED*NCLS + k];
                qt_dst[row] = s;
            }
        }
    }
}

// ===================== rank + gather ===============
__global__ void k_rank()
{
    __shared__ float ssc[NA];
    int t = threadIdx.x;
    if (t < NA) {
        float m = -1e30f;
        #pragma unroll
        for (int j = 0; j < NCLS; j++) m = fmaxf(m, g_cls[t*NCLS + j]);
        ssc[t] = m;
    }
    __syncthreads();
    if (t < NA) {
        float sc = ssc[t];
        int cnt = 0;
        for (int b = 0; b < NA; b++) {
            float sb = ssc[b];
            cnt += (sb > sc) || (sb == sc && b < t);
        }
        if (cnt < NSEL) g_sel[NTEMP + cnt] = t;
    }
}

__global__ void k_gather(const float* __restrict__ temp_inst,
                         const float* __restrict__ temp_anchor,
                         const unsigned char* __restrict__ mask)
{
    int r = blockIdx.x, t = threadIdx.x;
    bool m = mask[0] != 0;
    if (m) {
        if (r < NTEMP) {
            g_instB[r*ED + t] = temp_inst[r*ED + t];
            if (t < ADIM) g_anchorB[r*ADIM + t] = temp_anchor[r*ADIM + t];
        } else {
            int s = g_sel[r];
            g_instB[r*ED + t] = g_instA[s*ED + t];
            if (t < ADIM) g_anchorB[r*ADIM + t] = g_anchorA[s*ADIM + t];
        }
    } else {
        g_instB[r*ED + t] = g_instA[r*ED + t];
        if (t < ADIM) g_anchorB[r*ADIM + t] = g_anchorA[r*ADIM + t];
    }
}

// ===================== finalize ===========================================
__global__ void k_finalize(float* __restrict__ out,
                           const int* __restrict__ track_id,
                           const unsigned char* __restrict__ mask)
{
    int i = blockIdx.x*blockDim.x + threadIdx.x;
    if (i < NA*ED)   out[OFF_INST + i]   = g_instB[i];
    if (i < NA*ADIM) out[OFF_ANCHOR + i] = g_anchorB[i];
    if (i < NA) {
        bool m = mask[0] != 0;
        out[OFF_TRACK + i] = m ? (float)track_id[i] : -1.0f;
    }
}

// ===================== host ===============================================
extern "C" void kernel_launch(void* const* d_in, const int* in_sizes, int n_in,
                              void* d_out, int out_size)
{
    const float* feature      = (const float*)d_in[0];
    const int*   ss           = (const int*)d_in[1];
    const int*   lsi          = (const int*)d_in[2];
    const float* inst_in      = (const float*)d_in[3];
    const float* anchor_in    = (const float*)d_in[4];
    const float* ti           = (const float*)d_in[5];
    const float* temp_inst    = (const float*)d_in[6];
    const float* temp_anchor  = (const float*)d_in[7];
    const unsigned char* mask = (const unsigned char*)d_in[8];
    const int*   track_id     = (const int*)d_in[9];
    const float* image_wh     = (const float*)d_in[10];
    const float* l2i          = (const float*)d_in[11];
    const float* anchor_w     = (const float*)d_in[12];
    const float* anchor_b     = (const float*)d_in[13];
    const float* kps_w        = (const float*)d_in[14];
    const float* kps_b        = (const float*)d_in[15];
    const float* wfc_w        = (const float*)d_in[16];
    const float* wfc_b        = (const float*)d_in[17];
    const float* outp_w       = (const float*)d_in[18];
    const float* outp_b       = (const float*)d_in[19];
    const float* ffn_w        = (const float*)d_in[20];
    const float* ffn_b        = (const float*)d_in[21];
    const float* reg_w        = (const float*)d_in[22];
    const float* reg_b        = (const float*)d_in[23];
    const float* cls_w        = (const float*)d_in[24];
    const float* cls_b        = (const float*)d_in[25];
    const float* qt_w         = (const float*)d_in[26];
    const float* qt_b         = (const float*)d_in[27];

    int T = in_sizes[0] / (NC*ED);
    float* out = (float*)d_out;

    k_init<<<(NA*ED + 255)/256, 256>>>(inst_in, anchor_in);

    for (int i = 0; i < NDEC; i++) {
        int use_b = (i >= 1) ? 1 : 0;

        k1_embed_kps_proj<<<NA, 256>>>(anchor_w, anchor_b,
                                       kps_w + (size_t)i*ED*NLEARN*3,
                                       kps_b + (size_t)i*NLEARN*3,
                                       l2i, image_wh, use_b);

        dim3 g2(WTOT/BN, (NA + BM - 1)/BM);
        k2_wfc_gemm<<<g2, 256>>>(wfc_w + (size_t)i*ED*WTOT,
                                 wfc_b + (size_t)i*WTOT, use_b);

        float* feats = out + OFF_TMP + (size_t)i*NA*ED;
        k4_daf<<<NA, 256>>>(feature, ss, lsi, T, feats);

        int cls_mode = (i == 0) ? 1 : ((i == NDEC-1) ? 2 : 0);
        int qt_on    = (i == NDEC-1) ? 1 : 0;
        k5_tail<<<(NA + TR - 1)/TR, 256>>>(feats,
                    outp_w + (size_t)i*ED*ED,    outp_b + (size_t)i*ED,
                    ffn_w  + (size_t)i*2*ED*ED,  ffn_b  + (size_t)i*ED,
                    reg_w  + (size_t)i*ED*ADIM,  reg_b  + (size_t)i*ADIM,
                    cls_w  + (size_t)i*ED*NCLS,  cls_b  + (size_t)i*NCLS,
                    qt_w   + (size_t)i*ED,       qt_b   + (size_t)i,
                    ti, use_b, cls_mode, out + OFF_CLS, qt_on, out + OFF_QT);

        if (i == 0) {
            k_rank<<<1, 1024>>>();
            k_gather<<<NA, 256>>>(temp_inst, temp_anchor, mask);
        }
    }

    k_finalize<<<(NA*ED + 255)/256, 256>>>(out, track_id, mask);
}